// round 2
// baseline (speedup 1.0000x reference)
#include <cuda_runtime.h>
#include <math.h>

#define BF    512     // B*F = 8*64
#define NTOT  66      // N_TAUS + 2K
#define NOUT  50      // N_TAUS
#define KK    8
#define TILE  32
#define DT_F  0.05f

// ---------------- constant tables (computed on device each launch) ----------
__device__ double g_D[NTOT * NTOT];
__device__ double g_P[2][NTOT * NTOT];
__device__ float  g_band[17][NOUT];   // g_band[d][j] = POST[j+d][j+8]
__device__ float  g_sneg[NTOT];       // -(float)s_full[n]

__global__ void init_kernel() {
    int tid = threadIdx.x;
    const double c = pow(1000.0, 1.0 / 49.0);
    __shared__ double s[NTOT], tau[NTOT];
    if (tid < NTOT) {
        double e = (double)(tid - KK);
        double tv = 0.1 * pow(c, e);
        tau[tid] = tv;
        s[tid] = (double)KK / tv;
        // reference: S_FULL cast to f32, then negated when used
        g_sneg[tid] = -(float)s[tid];
    }
    __syncthreads();

    for (int idx = tid; idx < NTOT * NTOT; idx += blockDim.x) g_D[idx] = 0.0;
    __syncthreads();
    if (tid >= 1 && tid <= NTOT - 2) {
        double denom = s[tid + 1] - s[tid - 1];
        g_D[tid * NTOT + tid - 1] = -(1.0 / c) / denom;
        g_D[tid * NTOT + tid]     = (1.0 / c - c) / denom;
        g_D[tid * NTOT + tid + 1] = c / denom;
    }
    __syncthreads();

    for (int idx = tid; idx < NTOT * NTOT; idx += blockDim.x) g_P[1][idx] = g_D[idx];
    __syncthreads();

    // P_k = P_{k-1} * D, exploiting D's tridiagonal columns
    for (int k = 2; k <= KK; k++) {
        int src = (k - 1) & 1, dst = k & 1;
        for (int idx = tid; idx < NTOT * NTOT; idx += blockDim.x) {
            int i = idx / NTOT, j = idx % NTOT;
            double acc = g_P[src][i * NTOT + j] * g_D[j * NTOT + j];
            if (j > 0)        acc += g_P[src][i * NTOT + j - 1] * g_D[(j - 1) * NTOT + j];
            if (j < NTOT - 1) acc += g_P[src][i * NTOT + j + 1] * g_D[(j + 1) * NTOT + j];
            g_P[dst][idx] = acc;
        }
        __syncthreads();
    }
    const int fin = KK & 1;  // = 0

    // POST[n][m] = DK[m][n] * tau[m]^G * exp((K+1)*log(s[m]) - lgamma(K+1))
    double lg9 = lgamma(9.0);
    for (int idx = tid; idx < 17 * NOUT; idx += blockDim.x) {
        int d = idx / NOUT, j = idx % NOUT;
        int m = j + KK, n = j + d;
        double w = tau[m] * exp(9.0 * log(s[m]) - lg9);
        g_band[d][j] = (float)(g_P[fin][m * NTOT + n] * w);
    }
}

// ---------------- main fused log-domain scan + banded einsum ----------------
__global__ void __launch_bounds__(128) scan_kernel(
    const float* __restrict__ f, const float* __restrict__ alpha,
    const float* __restrict__ delta,
    float* __restrict__ til, float* __restrict__ hout, float* __restrict__ Fout,
    int T) {
    __shared__ float sh_x[TILE], sh_lf[TILE];
    __shared__ float sh_F[TILE][NTOT];

    const int cb  = blockIdx.x;   // chain index
    const int tid = threadIdx.x;

    const float sneg = (tid < NTOT) ? g_sneg[tid] : 0.0f;
    float carry = -INFINITY;      // log-domain carry, matches reference init

    // phase-2 mapping: 25 j-pair blocks x 5 t-groups = 125 active threads
    const int  jb   = tid % 25;
    const int  tq   = tid / 25;
    const bool act2 = (tid < 125);
    const int  jj   = 2 * jb;
    float c0[17], c1[17];
    if (act2) {
#pragma unroll
        for (int d = 0; d < 17; d++) { c0[d] = g_band[d][jj]; c1[d] = g_band[d][jj + 1]; }
    }

    for (int t0 = 0; t0 < T; t0 += TILE) {
        // ---- load phase ----
        if (tid < TILE) {
            int idx = (t0 + tid) * BF + cb;
            float fv = __ldg(&f[idx]);
            float av = __ldg(&alpha[idx]);
            float dv = __ldg(&delta[idx]);
            // exactly mirror reference fp32 op order (no FMA contraction):
            // x  = alpha*DT + delta ;  lf = log(f*DT)
            sh_x[tid]  = __fadd_rn(__fmul_rn(av, DT_F), dv);
            sh_lf[tid] = logf(__fmul_rn(fv, DT_F));
        }
        __syncthreads();

        // ---- phase 1: log-domain logaddexp scan (replicates jnp.logaddexp) ----
        if (tid < NTOT) {
#pragma unroll
            for (int j = 0; j < TILE; j++) {
                float ll = __fmul_rn(sh_x[j], sneg);      // log_lap = x * (-s)
                float lf = sh_lf[j];
                float a  = __fadd_rn(carry, ll);          // carry + ll
                float am = fmaxf(a, lf);
                float d  = __fsub_rn(a, lf);
                float r  = __fadd_rn(am, log1pf(expf(-fabsf(d))));
                carry = r;
                sh_F[j][tid] = expf(r);                   // F_exp = exp(log_F)
            }
        }
        __syncthreads();

        // ---- phase 2: 17-tap banded matvec + stores ----
        if (act2) {
            for (int tl = tq; tl < TILE; tl += 5) {
                const float* Fr = sh_F[tl];
                float a0 = 0.0f, a1 = 0.0f;
#pragma unroll
                for (int d = 0; d < 17; d++) {
                    a0 = fmaf(Fr[jj + d],     c0[d], a0);
                    a1 = fmaf(Fr[jj + 1 + d], c1[d], a1);
                }
                size_t base = ((size_t)(t0 + tl) * BF + cb) * NOUT + jj;
                *(float2*)(til  + base) = make_float2(a0, a1);
                *(float2*)(Fout + base) = make_float2(Fr[jj + KK], Fr[jj + KK + 1]);
            }
        }
    }

    // h = final log-domain carry (reference returns log-domain h)
    if (tid < NTOT) hout[(size_t)cb * NTOT + tid] = carry;
}

// ---------------- launch ----------------------------------------------------
extern "C" void kernel_launch(void* const* d_in, const int* in_sizes, int n_in,
                              void* d_out, int out_size) {
    const float* f     = (const float*)d_in[0];
    const float* alpha = (const float*)d_in[1];
    const float* delta = (const float*)d_in[2];
    int T = in_sizes[0] / BF;           // 2048

    float* out  = (float*)d_out;
    size_t tsz  = (size_t)T * BF * NOUT;
    float* til  = out;
    float* hptr = out + tsz;
    float* Fo   = out + tsz + (size_t)BF * NTOT;

    init_kernel<<<1, 256>>>();
    scan_kernel<<<BF, 128>>>(f, alpha, delta, til, hptr, Fo, T);
}

// round 3
// speedup vs baseline: 1.0395x; 1.0395x over previous
#include <cuda_runtime.h>
#include <math.h>

#define BF    512     // B*F = 8*64
#define NTOT  66      // N_TAUS + 2K
#define NOUT  50      // N_TAUS
#define KK    8
#define TILE  32
#define DT_F  0.05f
#define FPAD  68      // padded shF row (float2-friendly)

// ---------------- constant tables (computed on device each launch) ----------
__device__ double g_D[NTOT * NTOT];
__device__ double g_P[2][NTOT * NTOT];
__device__ float  g_band[17][NOUT];   // g_band[d][j] = POST[j+d][j+8]
__device__ float  g_sneg[NTOT];       // -(float)s_full[n]

__global__ void init_kernel() {
    int tid = threadIdx.x;
    const double c = pow(1000.0, 1.0 / 49.0);
    __shared__ double s[NTOT], tau[NTOT];
    if (tid < NTOT) {
        double e = (double)(tid - KK);
        double tv = 0.1 * pow(c, e);
        tau[tid] = tv;
        s[tid] = (double)KK / tv;
        g_sneg[tid] = -(float)s[tid];
    }
    __syncthreads();

    for (int idx = tid; idx < NTOT * NTOT; idx += blockDim.x) g_D[idx] = 0.0;
    __syncthreads();
    if (tid >= 1 && tid <= NTOT - 2) {
        double denom = s[tid + 1] - s[tid - 1];
        g_D[tid * NTOT + tid - 1] = -(1.0 / c) / denom;
        g_D[tid * NTOT + tid]     = (1.0 / c - c) / denom;
        g_D[tid * NTOT + tid + 1] = c / denom;
    }
    __syncthreads();

    for (int idx = tid; idx < NTOT * NTOT; idx += blockDim.x) g_P[1][idx] = g_D[idx];
    __syncthreads();

    for (int k = 2; k <= KK; k++) {
        int src = (k - 1) & 1, dst = k & 1;
        for (int idx = tid; idx < NTOT * NTOT; idx += blockDim.x) {
            int i = idx / NTOT, j = idx % NTOT;
            double acc = g_P[src][i * NTOT + j] * g_D[j * NTOT + j];
            if (j > 0)        acc += g_P[src][i * NTOT + j - 1] * g_D[(j - 1) * NTOT + j];
            if (j < NTOT - 1) acc += g_P[src][i * NTOT + j + 1] * g_D[(j + 1) * NTOT + j];
            g_P[dst][idx] = acc;
        }
        __syncthreads();
    }
    const int fin = KK & 1;  // = 0

    double lg9 = lgamma(9.0);
    for (int idx = tid; idx < 17 * NOUT; idx += blockDim.x) {
        int d = idx / NOUT, j = idx % NOUT;
        int m = j + KK, n = j + d;
        double w = tau[m] * exp(9.0 * log(s[m]) - lg9);
        g_band[d][j] = (float)(g_P[fin][m * NTOT + n] * w);
    }
}

// ---------------- banded matvec for one tile (inlined helper) ----------------
__device__ __forceinline__ void do_matvec(
    const float (*Ftile)[FPAD], int t0, int cb, int jj, int tq,
    const float* __restrict__ c0, const float* __restrict__ c1,
    float* __restrict__ til, float* __restrict__ Fout) {
    for (int tl = tq; tl < TILE; tl += 3) {
        const float* Fr = Ftile[tl];
        float2 v[9];
#pragma unroll
        for (int i = 0; i < 9; i++)
            v[i] = *(const float2*)(Fr + jj + 2 * i);
        float a0 = 0.0f, a1 = 0.0f;
#pragma unroll
        for (int i = 0; i < 9; i++) {
            a0 = fmaf(v[i].x, c0[2 * i], a0);
            a1 = fmaf(v[i].y, c1[2 * i], a1);
        }
#pragma unroll
        for (int i = 0; i < 8; i++) {
            a0 = fmaf(v[i].y,     c0[2 * i + 1], a0);
            a1 = fmaf(v[i + 1].x, c1[2 * i + 1], a1);
        }
        size_t base = ((size_t)(t0 + tl) * BF + cb) * NOUT + jj;
        __stcs((float2*)(til  + base), make_float2(a0, a1));
        __stcs((float2*)(Fout + base), make_float2(v[4].x, v[4].y));  // F[jj+8], F[jj+9]
    }
}

// ---------------- fused pipelined log-domain scan + banded einsum ------------
__global__ void __launch_bounds__(192) scan_kernel(
    const float* __restrict__ f, const float* __restrict__ alpha,
    const float* __restrict__ delta,
    float* __restrict__ til, float* __restrict__ hout, float* __restrict__ Fout,
    int T) {
    __shared__ float2 shXL[2][TILE];            // (x, log(f*DT)) per t
    __shared__ float  shF[2][TILE][FPAD];       // exp(log_F) tiles, double buffered

    const int cb  = blockIdx.x;
    const int tid = threadIdx.x;
    const int nt  = T / TILE;

    // roles
    const bool isScan = (tid < NTOT);                 // 66 scan lanes (warps 0-2)
    const bool isLoad = (tid >= NTOT && tid < 96);    // 30 loader threads (warp 2)
    const int  u      = tid - NTOT;                   // loader slot 0..29
    const int  tid2   = tid - 96;
    const bool mvAct  = (tid >= 96) && (tid2 < 75);   // 75 matvec threads (warps 3-5)
    const int  jb = mvAct ? (tid2 % 25) : 0;
    const int  tq = mvAct ? (tid2 / 25) : 0;
    const int  jj = 2 * jb;

    const float sneg = isScan ? g_sneg[tid] : 0.0f;
    float carry = -INFINITY;

    float c0[17], c1[17];
    if (mvAct) {
#pragma unroll
        for (int d = 0; d < 17; d++) { c0[d] = g_band[d][jj]; c1[d] = g_band[d][jj + 1]; }
    }

    // ---- prologue: load tile 0 inputs ----
    if (isLoad) {
#pragma unroll
        for (int r = 0; r < 2; r++) {
            int ti = u + r * 30;
            if (ti < TILE) {
                size_t idx = (size_t)ti * BF + cb;
                float fv = __ldg(&f[idx]);
                float av = __ldg(&alpha[idx]);
                float dv = __ldg(&delta[idx]);
                shXL[0][ti] = make_float2(__fadd_rn(__fmul_rn(av, DT_F), dv),
                                          logf(__fmul_rn(fv, DT_F)));
            }
        }
    }
    __syncthreads();

    for (int k = 0; k < nt; ++k) {
        const int cur = k & 1, prv = cur ^ 1;
        if (isScan) {
            // ---- log-domain logaddexp scan for tile k (bit-matches reference) ----
#pragma unroll 8
            for (int j = 0; j < TILE; ++j) {
                float2 xl = shXL[cur][j];
                float ll = __fmul_rn(xl.x, sneg);
                float a  = __fadd_rn(carry, ll);
                float am = fmaxf(a, xl.y);
                float dd = __fsub_rn(a, xl.y);
                carry = __fadd_rn(am, log1pf(expf(-fabsf(dd))));
                shF[cur][j][tid] = __expf(carry);
            }
        } else if (isLoad) {
            // ---- prefetch inputs for tile k+1 into the other buffer ----
            if (k + 1 < nt) {
                const int t0n = (k + 1) * TILE;
#pragma unroll
                for (int r = 0; r < 2; r++) {
                    int ti = u + r * 30;
                    if (ti < TILE) {
                        size_t idx = (size_t)(t0n + ti) * BF + cb;
                        float fv = __ldg(&f[idx]);
                        float av = __ldg(&alpha[idx]);
                        float dv = __ldg(&delta[idx]);
                        shXL[prv][ti] = make_float2(__fadd_rn(__fmul_rn(av, DT_F), dv),
                                                    logf(__fmul_rn(fv, DT_F)));
                    }
                }
            }
        } else if (mvAct) {
            // ---- consume tile k-1: 17-tap banded matvec + stores ----
            if (k > 0)
                do_matvec(shF[prv], (k - 1) * TILE, cb, jj, tq, c0, c1, til, Fout);
        }
        __syncthreads();
    }

    // ---- epilogue ----
    if (isScan) {
        hout[(size_t)cb * NTOT + tid] = carry;
    } else if (mvAct) {
        do_matvec(shF[(nt - 1) & 1], (nt - 1) * TILE, cb, jj, tq, c0, c1, til, Fout);
    }
}

// ---------------- launch ----------------------------------------------------
extern "C" void kernel_launch(void* const* d_in, const int* in_sizes, int n_in,
                              void* d_out, int out_size) {
    const float* f     = (const float*)d_in[0];
    const float* alpha = (const float*)d_in[1];
    const float* delta = (const float*)d_in[2];
    int T = in_sizes[0] / BF;           // 2048

    float* out  = (float*)d_out;
    size_t tsz  = (size_t)T * BF * NOUT;
    float* til  = out;
    float* hptr = out + tsz;
    float* Fo   = out + tsz + (size_t)BF * NTOT;

    init_kernel<<<1, 1024>>>();
    scan_kernel<<<BF, 192>>>(f, alpha, delta, til, hptr, Fo, T);
}